// round 1
// baseline (speedup 1.0000x reference)
#include <cuda_runtime.h>
#include <math.h>

#define NN   100000
#define FIN  1433
#define HH1  32
#define HH2  16
#define EE   3200000

// ---------------- scratch (__device__ globals; no allocations allowed) ----------
__device__ int   g_is64;
__device__ int   g_edges[2 * EE];          // converted int32 edges: [0..E)=src, [E..2E)=dst
__device__ int   g_deg[NN];
__device__ float g_dis[NN];
__device__ int   g_rowptr[NN + 1];
__device__ int   g_fill[NN];
__device__ int   g_col[EE];
__device__ int   g_bsum[128];
__device__ float g_g1[NN * HH1];
__device__ float g_h1[NN * HH1];
__device__ float g_g2[NN * HH2];
__device__ float g_h2[NN * HH2];

// ---------------- f32x2 helpers (sm_103a packed fp32) ---------------------------
__device__ __forceinline__ unsigned long long packf2(float x) {
    unsigned long long r;
    asm("mov.b64 %0, {%1, %1};" : "=l"(r) : "f"(x));
    return r;
}
__device__ __forceinline__ void ffma2(unsigned long long& d, unsigned long long a,
                                      unsigned long long b) {
    asm("fma.rn.f32x2 %0, %1, %2, %0;" : "+l"(d) : "l"(a), "l"(b));
}
__device__ __forceinline__ void unpackf2(unsigned long long p, float& lo, float& hi) {
    asm("mov.b64 {%0, %1}, %2;" : "=f"(lo), "=f"(hi) : "l"(p));
}

// ---------------- edge dtype detect + convert -----------------------------------
__global__ void detect_kernel(const unsigned int* __restrict__ p) {
    // int64 data -> every high word is 0 (values < 100000). int32 data -> the
    // "high word" position holds the next index, ~never 0 for 64 samples.
    int is64 = 1;
    for (int i = 0; i < 64; i++)
        if (p[2 * i + 1] != 0u) { is64 = 0; break; }
    g_is64 = is64;
}

__global__ void convert_kernel(const void* __restrict__ p) {
    int i = blockIdx.x * blockDim.x + threadIdx.x;
    if (i >= 2 * EE) return;
    int v;
    if (g_is64) v = (int)((const long long*)p)[i];
    else        v = ((const int*)p)[i];
    g_edges[i] = v;
}

// ---------------- degree / normalization / CSR ----------------------------------
__global__ void init_kernel() {
    int v = blockIdx.x * blockDim.x + threadIdx.x;
    if (v < NN) { g_deg[v] = 1; g_fill[v] = 0; }   // deg starts at 1 for self-loop
}

__global__ void degree_kernel() {
    int e = blockIdx.x * blockDim.x + threadIdx.x;
    if (e < EE) atomicAdd(&g_deg[g_edges[EE + e]], 1);
}

__global__ void disqrt_kernel() {
    int v = blockIdx.x * blockDim.x + threadIdx.x;
    if (v < NN) g_dis[v] = rsqrtf((float)g_deg[v]);
}

// exclusive scan of cnt[v] = deg[v]-1 into rowptr (3-kernel scheme)
__global__ void scan1_kernel() {
    __shared__ int s[1024];
    int tid = threadIdx.x;
    int v = blockIdx.x * 1024 + tid;
    int val = (v < NN) ? (g_deg[v] - 1) : 0;
    s[tid] = val;
    __syncthreads();
    for (int off = 1; off < 1024; off <<= 1) {
        int t = (tid >= off) ? s[tid - off] : 0;
        __syncthreads();
        s[tid] += t;
        __syncthreads();
    }
    if (v < NN) g_rowptr[v] = s[tid] - val;          // exclusive
    if (tid == 1023) g_bsum[blockIdx.x] = s[1023];
}

__global__ void scan2_kernel(int nblk) {
    if (threadIdx.x == 0 && blockIdx.x == 0) {
        int run = 0;
        for (int i = 0; i < nblk; i++) { int t = g_bsum[i]; g_bsum[i] = run; run += t; }
    }
}

__global__ void scan3_kernel() {
    int v = blockIdx.x * blockDim.x + threadIdx.x;
    if (v < NN)       g_rowptr[v] += g_bsum[v >> 10];
    else if (v == NN) g_rowptr[NN] = EE;
}

__global__ void fill_kernel() {
    int e = blockIdx.x * blockDim.x + threadIdx.x;
    if (e >= EE) return;
    int v   = g_edges[EE + e];
    int pos = atomicAdd(&g_fill[v], 1);
    g_col[g_rowptr[v] + pos] = g_edges[e];
}

// ---------------- GEMM1: g1 = x @ W1  [100000,1433]x[1433,32] -------------------
// W1 in smem (padded to 1440 rows, zeros), x tiles double-buffered through regs.
// Each thread: 1 row, 32 output cols as 16 f32x2 accumulators.
#define G1_SMEM ((1440 * 32 + 256 * 33) * 4)
__global__ void gemm1_kernel(const float* __restrict__ x, const float* __restrict__ W1) {
    extern __shared__ float sm[];
    float* Ws = sm;                 // [1440][32]
    float* xs = sm + 1440 * 32;     // [256][33]
    const int tid = threadIdx.x;
    for (int i = tid; i < 1440 * 32; i += 256)
        Ws[i] = (i < FIN * HH1) ? W1[i] : 0.f;
    const int row0 = blockIdx.x * 256;

    float xr[32];
    #pragma unroll
    for (int i = 0; i < 32; i++) {
        int idx = i * 256 + tid;
        int r = idx >> 5, c = idx & 31;
        int gr = row0 + r;
        xr[i] = (gr < NN) ? x[(size_t)gr * FIN + c] : 0.f;   // tile0: c<32<FIN always
    }
    unsigned long long acc[16];
    #pragma unroll
    for (int i = 0; i < 16; i++) acc[i] = 0ull;
    __syncthreads();   // Ws ready

    const int NT = (FIN + 31) / 32;   // 45
    for (int t = 0; t < NT; t++) {
        #pragma unroll
        for (int i = 0; i < 32; i++) {
            int idx = i * 256 + tid;
            int r = idx >> 5, c = idx & 31;
            xs[r * 33 + c] = xr[i];
        }
        __syncthreads();
        if (t + 1 < NT) {                     // prefetch next tile during compute
            int k0n = (t + 1) * 32;
            #pragma unroll
            for (int i = 0; i < 32; i++) {
                int idx = i * 256 + tid;
                int r = idx >> 5, c = idx & 31;
                int gr = row0 + r, k = k0n + c;
                xr[i] = (gr < NN && k < FIN) ? x[(size_t)gr * FIN + k] : 0.f;
            }
        }
        int k0 = t * 32;
        #pragma unroll 8
        for (int j = 0; j < 32; j++) {
            unsigned long long x2 = packf2(xs[tid * 33 + j]);
            const ulonglong2* wr = (const ulonglong2*)(Ws + (k0 + j) * 32);
            #pragma unroll
            for (int q = 0; q < 8; q++) {
                ulonglong2 w = wr[q];
                ffma2(acc[2 * q],     x2, w.x);
                ffma2(acc[2 * q + 1], x2, w.y);
            }
        }
        __syncthreads();
    }
    int row = row0 + tid;
    if (row < NN) {
        ulonglong2* o = (ulonglong2*)(g_g1 + (size_t)row * HH1);
        #pragma unroll
        for (int q = 0; q < 8; q++) o[q] = make_ulonglong2(acc[2 * q], acc[2 * q + 1]);
    }
}

// ---------------- aggregation layer 1 (warp per node, 32 cols) ------------------
__global__ void agg1_kernel(const float* __restrict__ b1) {
    int t = blockIdx.x * blockDim.x + threadIdx.x;
    int v = t >> 5, lane = t & 31;
    if (v >= NN) return;
    float dv  = g_dis[v];
    float acc = dv * g_g1[(size_t)v * HH1 + lane];   // self-loop term
    int b = g_rowptr[v], e = g_rowptr[v + 1];
    int i = b;
    for (; i + 4 <= e; i += 4) {
        int u0 = g_col[i], u1 = g_col[i + 1], u2 = g_col[i + 2], u3 = g_col[i + 3];
        float d0 = g_dis[u0], d1 = g_dis[u1], d2 = g_dis[u2], d3 = g_dis[u3];
        acc += d0 * g_g1[(size_t)u0 * HH1 + lane];
        acc += d1 * g_g1[(size_t)u1 * HH1 + lane];
        acc += d2 * g_g1[(size_t)u2 * HH1 + lane];
        acc += d3 * g_g1[(size_t)u3 * HH1 + lane];
    }
    for (; i < e; i++) {
        int u = g_col[i];
        acc += g_dis[u] * g_g1[(size_t)u * HH1 + lane];
    }
    float r = dv * acc + b1[lane];
    g_h1[(size_t)v * HH1 + lane] = fmaxf(r, 0.f);
}

// ---------------- GEMM2: g2 = h1 @ W2 [N,32]x[32,16] ----------------------------
__global__ void gemm2_kernel(const float* __restrict__ W2) {
    __shared__ float Ws[32 * 16];
    int tid = threadIdx.x;
    if (tid < 512) Ws[tid] = W2[tid];
    __syncthreads();
    int v = blockIdx.x * blockDim.x + tid;
    if (v >= NN) return;
    float h[32];
    const float4* hr = (const float4*)(g_h1 + (size_t)v * HH1);
    #pragma unroll
    for (int q = 0; q < 8; q++) {
        float4 f = hr[q];
        h[4 * q] = f.x; h[4 * q + 1] = f.y; h[4 * q + 2] = f.z; h[4 * q + 3] = f.w;
    }
    float o[16];
    #pragma unroll
    for (int c = 0; c < 16; c++) o[c] = 0.f;
    #pragma unroll
    for (int k = 0; k < 32; k++) {
        float hv = h[k];
        #pragma unroll
        for (int c = 0; c < 16; c++) o[c] += hv * Ws[k * 16 + c];
    }
    float4* op = (float4*)(g_g2 + (size_t)v * HH2);
    #pragma unroll
    for (int q = 0; q < 4; q++)
        op[q] = make_float4(o[4 * q], o[4 * q + 1], o[4 * q + 2], o[4 * q + 3]);
}

// ---------------- aggregation layer 2 (warp per node, 16 cols x 2 edges) --------
__global__ void agg2_kernel(const float* __restrict__ b2) {
    int t = blockIdx.x * blockDim.x + threadIdx.x;
    int v = t >> 5, lane = t & 31;
    if (v >= NN) return;
    int c = lane & 15, half = lane >> 4;
    float dv  = g_dis[v];
    float acc = (half == 0) ? dv * g_g2[(size_t)v * HH2 + c] : 0.f;
    int b = g_rowptr[v], e = g_rowptr[v + 1];
    for (int i = b + half; i < e; i += 2) {
        int u = g_col[i];
        acc += g_dis[u] * g_g2[(size_t)u * HH2 + c];
    }
    acc += __shfl_xor_sync(0xffffffffu, acc, 16);
    if (half == 0) {
        float r = dv * acc + b2[c];
        g_h2[(size_t)v * HH2 + c] = fmaxf(r, 0.f);
    }
}

// ---------------- final: out = log_softmax(h2 @ Wl + bl) ------------------------
#define WLROW 1436   // 1433 padded to /4
#define FB 64        // nodes per block
#define FIN_SMEM ((16 * WLROW + 1440 + 32) * 4)
__global__ void final_kernel(const float* __restrict__ Wl, const float* __restrict__ bl,
                             float* __restrict__ out) {
    extern __shared__ float sm[];
    float* Wls = sm;                    // [16][WLROW]
    float* bls = sm + 16 * WLROW;       // [1433] (+pad)
    float* red = bls + 1440;            // [32]
    const int tid = threadIdx.x, lane = tid & 31, wid = tid >> 5;
    for (int i = tid; i < 16 * WLROW; i += 256) {
        int k = i / WLROW, c = i % WLROW;
        Wls[i] = (c < FIN) ? Wl[k * FIN + c] : 0.f;
    }
    for (int i = tid; i < FIN; i += 256) bls[i] = bl[i];
    __syncthreads();

    for (int n = 0; n < FB; n++) {
        int v = blockIdx.x * FB + n;
        if (v >= NN) break;
        unsigned long long x2[16];
        #pragma unroll
        for (int k = 0; k < 16; k++) x2[k] = packf2(g_h2[(size_t)v * HH2 + k]);

        float lo[8];
        float lmax = -1e30f;
        #pragma unroll
        for (int g = 0; g < 2; g++) {
            int c4 = (tid + g * 256) * 4;
            if (c4 < WLROW) {
                unsigned long long a01 = 0ull, a23 = 0ull;
                #pragma unroll
                for (int k = 0; k < 16; k++) {
                    ulonglong2 w = *(const ulonglong2*)(Wls + k * WLROW + c4);
                    ffma2(a01, x2[k], w.x);
                    ffma2(a23, x2[k], w.y);
                }
                float f0, f1, f2, f3;
                unpackf2(a01, f0, f1);
                unpackf2(a23, f2, f3);
                float vv[4] = { f0, f1, f2, f3 };
                #pragma unroll
                for (int i2 = 0; i2 < 4; i2++) {
                    int c = c4 + i2;
                    float val = (c < FIN) ? (vv[i2] + bls[c]) : -1e30f;
                    lo[g * 4 + i2] = val;
                    lmax = fmaxf(lmax, val);
                }
            } else {
                #pragma unroll
                for (int i2 = 0; i2 < 4; i2++) lo[g * 4 + i2] = -1e30f;
            }
        }
        // block max
        float m = lmax;
        #pragma unroll
        for (int o = 16; o > 0; o >>= 1) m = fmaxf(m, __shfl_xor_sync(0xffffffffu, m, o));
        if (lane == 0) red[wid] = m;
        __syncthreads();
        if (tid < 8) {
            float mm = red[tid];
            #pragma unroll
            for (int o = 4; o > 0; o >>= 1) mm = fmaxf(mm, __shfl_xor_sync(0xffu, mm, o));
            if (tid == 0) red[0] = mm;
        }
        __syncthreads();
        float M = red[0];
        // block sum of exp
        float ls = 0.f;
        #pragma unroll
        for (int i2 = 0; i2 < 8; i2++) ls += expf(lo[i2] - M);
        #pragma unroll
        for (int o = 16; o > 0; o >>= 1) ls += __shfl_xor_sync(0xffffffffu, ls, o);
        __syncthreads();            // everyone read M before red reuse
        if (lane == 0) red[wid] = ls;
        __syncthreads();
        if (tid < 8) {
            float ss = red[tid];
            #pragma unroll
            for (int o = 4; o > 0; o >>= 1) ss += __shfl_xor_sync(0xffu, ss, o);
            if (tid == 0) red[0] = ss;
        }
        __syncthreads();
        float lse = M + logf(red[0]);
        #pragma unroll
        for (int g = 0; g < 2; g++) {
            int c4 = (tid + g * 256) * 4;
            #pragma unroll
            for (int i2 = 0; i2 < 4; i2++) {
                int c = c4 + i2;
                if (c < FIN) out[(size_t)v * FIN + c] = lo[g * 4 + i2] - lse;
            }
        }
        __syncthreads();            // red reuse next node
    }
}

// ---------------- launch --------------------------------------------------------
static inline int cdiv(int a, int b) { return (a + b - 1) / b; }

extern "C" void kernel_launch(void* const* d_in, const int* in_sizes, int n_in,
                              void* d_out, int out_size) {
    const float* x  = (const float*)d_in[0];
    const float* W1 = (const float*)d_in[1];
    const float* b1 = (const float*)d_in[2];
    const float* W2 = (const float*)d_in[3];
    const float* b2 = (const float*)d_in[4];
    const float* Wl = (const float*)d_in[5];
    const float* bl = (const float*)d_in[6];
    const void*  ei = d_in[7];
    float* out = (float*)d_out;

    cudaFuncSetAttribute(gemm1_kernel, cudaFuncAttributeMaxDynamicSharedMemorySize, G1_SMEM);
    cudaFuncSetAttribute(final_kernel, cudaFuncAttributeMaxDynamicSharedMemorySize, FIN_SMEM);

    detect_kernel<<<1, 1>>>((const unsigned int*)ei);
    convert_kernel<<<cdiv(2 * EE, 256), 256>>>(ei);
    init_kernel<<<cdiv(NN, 256), 256>>>();
    degree_kernel<<<cdiv(EE, 256), 256>>>();
    disqrt_kernel<<<cdiv(NN, 256), 256>>>();
    int nblk = cdiv(NN, 1024);
    scan1_kernel<<<nblk, 1024>>>();
    scan2_kernel<<<1, 32>>>(nblk);
    scan3_kernel<<<cdiv(NN + 1, 256), 256>>>();
    fill_kernel<<<cdiv(EE, 256), 256>>>();

    gemm1_kernel<<<cdiv(NN, 256), 256, G1_SMEM>>>(x, W1);
    agg1_kernel<<<cdiv(NN * 32, 256), 256>>>(b1);
    gemm2_kernel<<<cdiv(NN, 256), 256>>>(W2);
    agg2_kernel<<<cdiv(NN * 32, 256), 256>>>(b2);
    final_kernel<<<cdiv(NN, FB), 256, FIN_SMEM>>>(Wl, bl, out);
}

// round 4
// speedup vs baseline: 1.0990x; 1.0990x over previous
#include <cuda_runtime.h>
#include <math.h>

#define NN   100000
#define FIN  1433
#define HH1  32
#define HH2  16
#define EE   3200000

// ---------------- scratch (__device__ globals; no allocations allowed) ----------
__device__ int   g_is64;
__device__ int   g_edges[2 * EE];          // converted int32 edges: [0..E)=src, [E..2E)=dst
__device__ int   g_deg[NN];
__device__ float g_dis[NN];
__device__ int   g_rowptr[NN + 1];
__device__ int   g_fill[NN];
__device__ int   g_col[EE];
__device__ int   g_bsum[128];
__device__ float g_g1[NN * HH1];
__device__ float g_h1[NN * HH1];
__device__ float g_g2[NN * HH2];
__device__ float g_h2[NN * HH2];

// ---------------- f32x2 + tf32 helpers (sm_103a) --------------------------------
__device__ __forceinline__ unsigned long long packf2(float x) {
    unsigned long long r;
    asm("mov.b64 %0, {%1, %1};" : "=l"(r) : "f"(x));
    return r;
}
__device__ __forceinline__ void ffma2(unsigned long long& d, unsigned long long a,
                                      unsigned long long b) {
    asm("fma.rn.f32x2 %0, %1, %2, %0;" : "+l"(d) : "l"(a), "l"(b));
}
__device__ __forceinline__ void unpackf2(unsigned long long p, float& lo, float& hi) {
    asm("mov.b64 {%0, %1}, %2;" : "=f"(lo), "=f"(hi) : "l"(p));
}
__device__ __forceinline__ float tf32r(float x) {
    float r;
    asm("cvt.rna.tf32.f32 %0, %1;" : "=f"(r) : "f"(x));
    return r;
}

// ---------------- edge dtype detect + convert -----------------------------------
__global__ void detect_kernel(const unsigned int* __restrict__ p) {
    int is64 = 1;
    for (int i = 0; i < 64; i++)
        if (p[2 * i + 1] != 0u) { is64 = 0; break; }
    g_is64 = is64;
}

__global__ void convert_kernel(const void* __restrict__ p) {
    int i = blockIdx.x * blockDim.x + threadIdx.x;
    if (i >= 2 * EE) return;
    int v;
    if (g_is64) v = (int)((const long long*)p)[i];
    else        v = ((const int*)p)[i];
    g_edges[i] = v;
}

// ---------------- degree / normalization / CSR ----------------------------------
__global__ void init_kernel() {
    int v = blockIdx.x * blockDim.x + threadIdx.x;
    if (v < NN) { g_deg[v] = 1; g_fill[v] = 0; }   // deg starts at 1 for self-loop
}

__global__ void degree_kernel() {
    int e = blockIdx.x * blockDim.x + threadIdx.x;
    if (e < EE) atomicAdd(&g_deg[g_edges[EE + e]], 1);
}

__global__ void disqrt_kernel() {
    int v = blockIdx.x * blockDim.x + threadIdx.x;
    if (v < NN) g_dis[v] = rsqrtf((float)g_deg[v]);
}

__global__ void scan1_kernel() {
    __shared__ int s[1024];
    int tid = threadIdx.x;
    int v = blockIdx.x * 1024 + tid;
    int val = (v < NN) ? (g_deg[v] - 1) : 0;
    s[tid] = val;
    __syncthreads();
    for (int off = 1; off < 1024; off <<= 1) {
        int t = (tid >= off) ? s[tid - off] : 0;
        __syncthreads();
        s[tid] += t;
        __syncthreads();
    }
    if (v < NN) g_rowptr[v] = s[tid] - val;          // exclusive
    if (tid == 1023) g_bsum[blockIdx.x] = s[1023];
}

__global__ void scan2_kernel(int nblk) {
    if (threadIdx.x == 0 && blockIdx.x == 0) {
        int run = 0;
        for (int i = 0; i < nblk; i++) { int t = g_bsum[i]; g_bsum[i] = run; run += t; }
    }
}

__global__ void scan3_kernel() {
    int v = blockIdx.x * blockDim.x + threadIdx.x;
    if (v < NN)       g_rowptr[v] += g_bsum[v >> 10];
    else if (v == NN) g_rowptr[NN] = EE;
}

__global__ void fill_kernel() {
    int e = blockIdx.x * blockDim.x + threadIdx.x;
    if (e >= EE) return;
    int v   = g_edges[EE + e];
    int pos = atomicAdd(&g_fill[v], 1);
    g_col[g_rowptr[v] + pos] = g_edges[e];
}

// ---------------- GEMM1: g1 = x @ W1  [100000,1433]x[1433,32] -------------------
__global__ void __launch_bounds__(256, 4)
gemm1_kernel(const float* __restrict__ x, const float* __restrict__ W1) {
    __shared__ float xs[256 * 33];
    __shared__ __align__(16) float Ws[32 * 32];
    const int tid = threadIdx.x;
    const int row0 = blockIdx.x * 256;

    unsigned long long acc[16];
    #pragma unroll
    for (int i = 0; i < 16; i++) acc[i] = 0ull;

    const int NT = (FIN + 31) / 32;   // 45
    for (int t = 0; t < NT; t++) {
        const int k0 = t * 32;
        __syncthreads();               // previous compute done reading xs/Ws
        #pragma unroll 8
        for (int i = 0; i < 32; i++) {
            int idx = i * 256 + tid;
            int r = idx >> 5, c = idx & 31;
            int gr = row0 + r, k = k0 + c;
            float v = (gr < NN && k < FIN) ? x[(size_t)gr * FIN + k] : 0.f;
            xs[r * 33 + c] = tf32r(v);
        }
        {
            int i = tid * 4;
            int krow = k0 + (i >> 5);
            float4 w = make_float4(0.f, 0.f, 0.f, 0.f);
            if (krow < FIN) w = *(const float4*)(W1 + (size_t)k0 * 32 + i);
            w.x = tf32r(w.x); w.y = tf32r(w.y); w.z = tf32r(w.z); w.w = tf32r(w.w);
            *(float4*)&Ws[i] = w;
        }
        __syncthreads();
        #pragma unroll 8
        for (int j = 0; j < 32; j++) {
            unsigned long long x2 = packf2(xs[tid * 33 + j]);
            const ulonglong2* wr = (const ulonglong2*)(Ws + j * 32);
            #pragma unroll
            for (int q = 0; q < 8; q++) {
                ulonglong2 w = wr[q];
                ffma2(acc[2 * q],     x2, w.x);
                ffma2(acc[2 * q + 1], x2, w.y);
            }
        }
    }
    int row = row0 + tid;
    if (row < NN) {
        ulonglong2* o = (ulonglong2*)(g_g1 + (size_t)row * HH1);
        #pragma unroll
        for (int q = 0; q < 8; q++) o[q] = make_ulonglong2(acc[2 * q], acc[2 * q + 1]);
    }
}

// ---------------- aggregation layer 1 (warp per node, 32 cols) ------------------
__global__ void agg1_kernel(const float* __restrict__ b1) {
    int t = blockIdx.x * blockDim.x + threadIdx.x;
    int v = t >> 5, lane = t & 31;
    if (v >= NN) return;
    float dv  = g_dis[v];
    float acc = dv * g_g1[(size_t)v * HH1 + lane];   // self-loop term
    int b = g_rowptr[v], e = g_rowptr[v + 1];
    int i = b;
    for (; i + 4 <= e; i += 4) {
        int u0 = g_col[i], u1 = g_col[i + 1], u2 = g_col[i + 2], u3 = g_col[i + 3];
        float d0 = g_dis[u0], d1 = g_dis[u1], d2 = g_dis[u2], d3 = g_dis[u3];
        acc += d0 * g_g1[(size_t)u0 * HH1 + lane];
        acc += d1 * g_g1[(size_t)u1 * HH1 + lane];
        acc += d2 * g_g1[(size_t)u2 * HH1 + lane];
        acc += d3 * g_g1[(size_t)u3 * HH1 + lane];
    }
    for (; i < e; i++) {
        int u = g_col[i];
        acc += g_dis[u] * g_g1[(size_t)u * HH1 + lane];
    }
    float r = dv * acc + b1[lane];
    g_h1[(size_t)v * HH1 + lane] = fmaxf(r, 0.f);
}

// ---------------- GEMM2: g2 = h1 @ W2 [N,32]x[32,16], TF32 inputs ---------------
// FIX: load ALL 512 W2 elements (256-thread block loads 2 each). Previous rounds
// left Ws[256..511] as stale smem -> half of W2 was garbage/zero.
__global__ void gemm2_kernel(const float* __restrict__ W2) {
    __shared__ float Ws[32 * 16];
    int tid = threadIdx.x;
    #pragma unroll
    for (int i = tid; i < 32 * 16; i += 256) Ws[i] = tf32r(W2[i]);
    __syncthreads();
    int v = blockIdx.x * blockDim.x + tid;
    if (v >= NN) return;
    float h[32];
    const float4* hr = (const float4*)(g_h1 + (size_t)v * HH1);
    #pragma unroll
    for (int q = 0; q < 8; q++) {
        float4 f = hr[q];
        h[4 * q]     = tf32r(f.x);
        h[4 * q + 1] = tf32r(f.y);
        h[4 * q + 2] = tf32r(f.z);
        h[4 * q + 3] = tf32r(f.w);
    }
    float o[16];
    #pragma unroll
    for (int c = 0; c < 16; c++) o[c] = 0.f;
    #pragma unroll
    for (int k = 0; k < 32; k++) {
        float hv = h[k];
        #pragma unroll
        for (int c = 0; c < 16; c++) o[c] += hv * Ws[k * 16 + c];
    }
    float4* op = (float4*)(g_g2 + (size_t)v * HH2);
    #pragma unroll
    for (int q = 0; q < 4; q++)
        op[q] = make_float4(o[4 * q], o[4 * q + 1], o[4 * q + 2], o[4 * q + 3]);
}

// ---------------- aggregation layer 2 (warp per node, 16 cols x 2 edges) --------
__global__ void agg2_kernel(const float* __restrict__ b2) {
    int t = blockIdx.x * blockDim.x + threadIdx.x;
    int v = t >> 5, lane = t & 31;
    if (v >= NN) return;
    int c = lane & 15, half = lane >> 4;
    float dv  = g_dis[v];
    float acc = (half == 0) ? dv * g_g2[(size_t)v * HH2 + c] : 0.f;
    int b = g_rowptr[v], e = g_rowptr[v + 1];
    for (int i = b + half; i < e; i += 2) {
        int u = g_col[i];
        acc += g_dis[u] * g_g2[(size_t)u * HH2 + c];
    }
    acc += __shfl_xor_sync(0xffffffffu, acc, 16);
    if (half == 0) {
        float r = dv * acc + b2[c];
        g_h2[(size_t)v * HH2 + c] = fmaxf(r, 0.f);
    }
}

// ---------------- final: out = log_softmax(h2 @ Wl + bl), TF32 GEMM inputs ------
#define WCOL 1536
#define FB2  64        // nodes per block (8 batches of 8)
#define FIN_SMEM ((16 * WCOL + WCOL + 128 + 80) * 4)
__global__ void __launch_bounds__(256, 2)
final_kernel(const float* __restrict__ Wl, const float* __restrict__ bl,
             float* __restrict__ out) {
    extern __shared__ float sm[];
    float* Wls = sm;                        // [16][1536]
    float* bls = Wls + 16 * WCOL;           // [1536]
    float* h2s = bls + WCOL;                // [16][8] k-major (8B-aligned)
    float* red = h2s + 128;                 // [80]
    const int tid = threadIdx.x, lane = tid & 31, wid = tid >> 5;

    for (int i = tid; i < 16 * WCOL; i += 256) {
        int k = i / WCOL, c = i - k * WCOL;
        Wls[i] = (c < FIN) ? tf32r(Wl[k * FIN + c]) : 0.f;
    }
    for (int c = tid; c < WCOL; c += 256) bls[c] = (c < FIN) ? bl[c] : -1e30f;

    for (int bt = 0; bt < 8; bt++) {
        const int v0 = blockIdx.x * FB2 + bt * 8;
        __syncthreads();                    // previous batch done with h2s/red
        if (tid < 128) {
            int k = tid >> 3, n = tid & 7;
            int v = v0 + n;
            h2s[k * 8 + n] = (v < NN) ? tf32r(g_h2[(size_t)v * HH2 + k]) : 0.f;
        }
        __syncthreads();

        unsigned long long acc[6][4];
        #pragma unroll
        for (int j = 0; j < 6; j++)
            #pragma unroll
            for (int p = 0; p < 4; p++) acc[j][p] = 0ull;

        #pragma unroll 4
        for (int k = 0; k < 16; k++) {
            unsigned long long hp[4];
            #pragma unroll
            for (int p = 0; p < 4; p++)
                hp[p] = *(const unsigned long long*)(h2s + k * 8 + 2 * p);
            #pragma unroll
            for (int j = 0; j < 6; j++) {
                unsigned long long wp = packf2(Wls[k * WCOL + j * 256 + tid]);
                #pragma unroll
                for (int p = 0; p < 4; p++) ffma2(acc[j][p], hp[p], wp);
            }
        }

        float val[6][8];
        float lmax[8];
        #pragma unroll
        for (int n = 0; n < 8; n++) lmax[n] = -3e30f;
        #pragma unroll
        for (int j = 0; j < 6; j++) {
            float bb = bls[j * 256 + tid];
            #pragma unroll
            for (int p = 0; p < 4; p++) {
                float a, b;
                unpackf2(acc[j][p], a, b);
                float va = a + bb, vb = b + bb;
                val[j][2 * p]     = va;
                val[j][2 * p + 1] = vb;
                lmax[2 * p]     = fmaxf(lmax[2 * p], va);
                lmax[2 * p + 1] = fmaxf(lmax[2 * p + 1], vb);
            }
        }
        #pragma unroll
        for (int n = 0; n < 8; n++)
            #pragma unroll
            for (int o = 16; o > 0; o >>= 1)
                lmax[n] = fmaxf(lmax[n], __shfl_xor_sync(0xffffffffu, lmax[n], o));
        if (lane == 0)
            #pragma unroll
            for (int n = 0; n < 8; n++) red[wid * 8 + n] = lmax[n];
        __syncthreads();
        if (tid < 8) {
            float m = -3e30f;
            #pragma unroll
            for (int w = 0; w < 8; w++) m = fmaxf(m, red[w * 8 + tid]);
            red[64 + tid] = m;
        }
        __syncthreads();
        float M[8];
        #pragma unroll
        for (int n = 0; n < 8; n++) M[n] = red[64 + n];
        float ls[8];
        #pragma unroll
        for (int n = 0; n < 8; n++) ls[n] = 0.f;
        #pragma unroll
        for (int j = 0; j < 6; j++)
            #pragma unroll
            for (int n = 0; n < 8; n++) ls[n] += expf(val[j][n] - M[n]);
        #pragma unroll
        for (int n = 0; n < 8; n++)
            #pragma unroll
            for (int o = 16; o > 0; o >>= 1)
                ls[n] += __shfl_xor_sync(0xffffffffu, ls[n], o);
        if (lane == 0)
            #pragma unroll
            for (int n = 0; n < 8; n++) red[wid * 8 + n] = ls[n];
        __syncthreads();
        if (tid < 8) {
            float s = 0.f;
            #pragma unroll
            for (int w = 0; w < 8; w++) s += red[w * 8 + tid];
            red[72 + tid] = red[64 + tid] + logf(s);   // lse
        }
        __syncthreads();
        float lse[8];
        #pragma unroll
        for (int n = 0; n < 8; n++) lse[n] = red[72 + n];

        #pragma unroll
        for (int j = 0; j < 6; j++) {
            int col = j * 256 + tid;
            if (col < FIN) {
                #pragma unroll
                for (int n = 0; n < 8; n++) {
                    int v = v0 + n;
                    if (v < NN) out[(size_t)v * FIN + col] = val[j][n] - lse[n];
                }
            }
        }
    }
}

// ---------------- launch --------------------------------------------------------
static inline int cdiv(int a, int b) { return (a + b - 1) / b; }

extern "C" void kernel_launch(void* const* d_in, const int* in_sizes, int n_in,
                              void* d_out, int out_size) {
    const float* x  = (const float*)d_in[0];
    const float* W1 = (const float*)d_in[1];
    const float* b1 = (const float*)d_in[2];
    const float* W2 = (const float*)d_in[3];
    const float* b2 = (const float*)d_in[4];
    const float* Wl = (const float*)d_in[5];
    const float* bl = (const float*)d_in[6];
    const void*  ei = d_in[7];
    float* out = (float*)d_out;

    cudaFuncSetAttribute(final_kernel, cudaFuncAttributeMaxDynamicSharedMemorySize, FIN_SMEM);

    // launches 1-5, then gemm1 is launch #6 so `ncu -s 5 -c 1` profiles it
    detect_kernel<<<1, 1>>>((const unsigned int*)ei);
    convert_kernel<<<cdiv(2 * EE, 256), 256>>>(ei);
    init_kernel<<<cdiv(NN, 256), 256>>>();
    degree_kernel<<<cdiv(EE, 256), 256>>>();
    disqrt_kernel<<<cdiv(NN, 256), 256>>>();

    gemm1_kernel<<<cdiv(NN, 256), 256>>>(x, W1);

    // CSR build (needed only by agg kernels)
    int nblk = cdiv(NN, 1024);
    scan1_kernel<<<nblk, 1024>>>();
    scan2_kernel<<<1, 32>>>(nblk);
    scan3_kernel<<<cdiv(NN + 1, 256), 256>>>();
    fill_kernel<<<cdiv(EE, 256), 256>>>();

    agg1_kernel<<<cdiv(NN * 32, 256), 256>>>(b1);
    gemm2_kernel<<<cdiv(NN, 256), 256>>>(W2);
    agg2_kernel<<<cdiv(NN * 32, 256), 256>>>(b2);
    final_kernel<<<cdiv(NN, FB2), 256, FIN_SMEM>>>(Wl, bl, out);
}

// round 5
// speedup vs baseline: 1.1087x; 1.0089x over previous
#include <cuda_runtime.h>
#include <math.h>

#define NN   100000
#define FIN  1433
#define HH1  32
#define HH2  16
#define EE   3200000

// ---------------- scratch (__device__ globals; no allocations allowed) ----------
__device__ int   g_is64;
__device__ int   g_edges[2 * EE];          // converted int32 edges: [0..E)=src, [E..2E)=dst
__device__ int   g_deg[NN];
__device__ float g_dis[NN];
__device__ int   g_rowptr[NN + 1];
__device__ int   g_fill[NN];
__device__ int   g_col[EE];
__device__ int   g_bsum[128];
__device__ float g_g1[NN * HH1];
__device__ float g_g2[NN * HH2];
__device__ float g_h2[NN * HH2];

// ---------------- f32x2 + tf32 helpers (sm_103a) --------------------------------
__device__ __forceinline__ unsigned long long packf2(float x) {
    unsigned long long r;
    asm("mov.b64 %0, {%1, %1};" : "=l"(r) : "f"(x));
    return r;
}
__device__ __forceinline__ void ffma2(unsigned long long& d, unsigned long long a,
                                      unsigned long long b) {
    asm("fma.rn.f32x2 %0, %1, %2, %0;" : "+l"(d) : "l"(a), "l"(b));
}
__device__ __forceinline__ void unpackf2(unsigned long long p, float& lo, float& hi) {
    asm("mov.b64 {%0, %1}, %2;" : "=f"(lo), "=f"(hi) : "l"(p));
}
__device__ __forceinline__ float tf32r(float x) {
    float r;
    asm("cvt.rna.tf32.f32 %0, %1;" : "=f"(r) : "f"(x));
    return r;
}

// ---------------- edge dtype detect + convert -----------------------------------
__global__ void detect_kernel(const unsigned int* __restrict__ p) {
    int is64 = 1;
    for (int i = 0; i < 64; i++)
        if (p[2 * i + 1] != 0u) { is64 = 0; break; }
    g_is64 = is64;
}

__global__ void convert_kernel(const void* __restrict__ p) {
    int i = blockIdx.x * blockDim.x + threadIdx.x;
    if (i >= 2 * EE) return;
    int v;
    if (g_is64) v = (int)((const long long*)p)[i];
    else        v = ((const int*)p)[i];
    g_edges[i] = v;
}

// ---------------- degree / normalization / CSR ----------------------------------
__global__ void init_kernel() {
    int v = blockIdx.x * blockDim.x + threadIdx.x;
    if (v < NN) { g_deg[v] = 1; g_fill[v] = 0; }   // deg starts at 1 for self-loop
}

__global__ void degree_kernel() {
    int e = blockIdx.x * blockDim.x + threadIdx.x;
    if (e < EE) atomicAdd(&g_deg[g_edges[EE + e]], 1);
}

// scan1 also computes g_dis (fused disqrt)
__global__ void scan1_kernel() {
    __shared__ int s[1024];
    int tid = threadIdx.x;
    int v = blockIdx.x * 1024 + tid;
    int d = (v < NN) ? g_deg[v] : 1;
    int val = (v < NN) ? (d - 1) : 0;
    s[tid] = val;
    __syncthreads();
    for (int off = 1; off < 1024; off <<= 1) {
        int t = (tid >= off) ? s[tid - off] : 0;
        __syncthreads();
        s[tid] += t;
        __syncthreads();
    }
    if (v < NN) {
        g_rowptr[v] = s[tid] - val;          // exclusive
        g_dis[v] = rsqrtf((float)d);
    }
    if (tid == 1023) g_bsum[blockIdx.x] = s[1023];
}

__global__ void scan2_kernel(int nblk) {
    if (threadIdx.x == 0 && blockIdx.x == 0) {
        int run = 0;
        for (int i = 0; i < nblk; i++) { int t = g_bsum[i]; g_bsum[i] = run; run += t; }
    }
}

__global__ void scan3_kernel() {
    int v = blockIdx.x * blockDim.x + threadIdx.x;
    if (v < NN)       g_rowptr[v] += g_bsum[v >> 10];
    else if (v == NN) g_rowptr[NN] = EE;
}

__global__ void fill_kernel() {
    int e = blockIdx.x * blockDim.x + threadIdx.x;
    if (e >= EE) return;
    int v   = g_edges[EE + e];
    int pos = atomicAdd(&g_fill[v], 1);
    g_col[g_rowptr[v] + pos] = g_edges[e];
}

// ---------------- GEMM1: g1 = x @ W1  [100000,1433]x[1433,32] -------------------
__global__ void __launch_bounds__(256, 4)
gemm1_kernel(const float* __restrict__ x, const float* __restrict__ W1) {
    __shared__ float xs[256 * 33];
    __shared__ __align__(16) float Ws[32 * 32];
    const int tid = threadIdx.x;
    const int row0 = blockIdx.x * 256;

    unsigned long long acc[16];
    #pragma unroll
    for (int i = 0; i < 16; i++) acc[i] = 0ull;

    const int NT = (FIN + 31) / 32;   // 45
    for (int t = 0; t < NT; t++) {
        const int k0 = t * 32;
        __syncthreads();               // previous compute done reading xs/Ws
        #pragma unroll 8
        for (int i = 0; i < 32; i++) {
            int idx = i * 256 + tid;
            int r = idx >> 5, c = idx & 31;
            int gr = row0 + r, k = k0 + c;
            float v = (gr < NN && k < FIN) ? x[(size_t)gr * FIN + k] : 0.f;
            xs[r * 33 + c] = tf32r(v);
        }
        {
            int i = tid * 4;
            int krow = k0 + (i >> 5);
            float4 w = make_float4(0.f, 0.f, 0.f, 0.f);
            if (krow < FIN) w = *(const float4*)(W1 + (size_t)k0 * 32 + i);
            w.x = tf32r(w.x); w.y = tf32r(w.y); w.z = tf32r(w.z); w.w = tf32r(w.w);
            *(float4*)&Ws[i] = w;
        }
        __syncthreads();
        #pragma unroll 8
        for (int j = 0; j < 32; j++) {
            unsigned long long x2 = packf2(xs[tid * 33 + j]);
            const ulonglong2* wr = (const ulonglong2*)(Ws + j * 32);
            #pragma unroll
            for (int q = 0; q < 8; q++) {
                ulonglong2 w = wr[q];
                ffma2(acc[2 * q],     x2, w.x);
                ffma2(acc[2 * q + 1], x2, w.y);
            }
        }
    }
    int row = row0 + tid;
    if (row < NN) {
        ulonglong2* o = (ulonglong2*)(g_g1 + (size_t)row * HH1);
        #pragma unroll
        for (int q = 0; q < 8; q++) o[q] = make_ulonglong2(acc[2 * q], acc[2 * q + 1]);
    }
}

// ------- aggregation layer 1 + fused GEMM2 (warp per node) ----------------------
// h1[v] = relu(dv*(sum)+b1) computed per lane; then g2[v] = tf32(h1[v]) @ W2
// via warp shuffle broadcast. g_h1 never hits global memory.
__global__ void agg1_kernel(const float* __restrict__ b1, const float* __restrict__ W2) {
    __shared__ float W2s[32 * 16];
    __shared__ float b1s[32];
    {
        int tid = threadIdx.x;
        for (int i = tid; i < 32 * 16; i += 256) W2s[i] = tf32r(W2[i]);
        if (tid < 32) b1s[tid] = b1[tid];
    }
    __syncthreads();

    int t = blockIdx.x * blockDim.x + threadIdx.x;
    int v = t >> 5, lane = t & 31;
    if (v >= NN) return;
    float dv  = g_dis[v];
    float acc = dv * g_g1[(size_t)v * HH1 + lane];   // self-loop term
    int b = g_rowptr[v], e = g_rowptr[v + 1];
    int i = b;
    for (; i + 4 <= e; i += 4) {
        int u0 = g_col[i], u1 = g_col[i + 1], u2 = g_col[i + 2], u3 = g_col[i + 3];
        float d0 = g_dis[u0], d1 = g_dis[u1], d2 = g_dis[u2], d3 = g_dis[u3];
        acc += d0 * g_g1[(size_t)u0 * HH1 + lane];
        acc += d1 * g_g1[(size_t)u1 * HH1 + lane];
        acc += d2 * g_g1[(size_t)u2 * HH1 + lane];
        acc += d3 * g_g1[(size_t)u3 * HH1 + lane];
    }
    for (; i < e; i++) {
        int u = g_col[i];
        acc += g_dis[u] * g_g1[(size_t)u * HH1 + lane];
    }
    float h = tf32r(fmaxf(dv * acc + b1s[lane], 0.f));

    // fused gemm2: o[c] = sum_k h[k] * W2[k][c]; lanes split k-range in halves
    int c = lane & 15, half = lane >> 4;
    float o = 0.f;
    #pragma unroll
    for (int k = 0; k < 16; k++) {
        int kk = half * 16 + k;
        float hv = __shfl_sync(0xffffffffu, h, kk);
        o += hv * W2s[kk * 16 + c];
    }
    o += __shfl_xor_sync(0xffffffffu, o, 16);
    if (half == 0) g_g2[(size_t)v * HH2 + c] = o;
}

// ---------------- aggregation layer 2 (warp per node, 16 cols x 2 edges) --------
__global__ void agg2_kernel(const float* __restrict__ b2) {
    int t = blockIdx.x * blockDim.x + threadIdx.x;
    int v = t >> 5, lane = t & 31;
    if (v >= NN) return;
    int c = lane & 15, half = lane >> 4;
    float dv  = g_dis[v];
    float acc = (half == 0) ? dv * g_g2[(size_t)v * HH2 + c] : 0.f;
    int b = g_rowptr[v], e = g_rowptr[v + 1];
    for (int i = b + half; i < e; i += 2) {
        int u = g_col[i];
        acc += g_dis[u] * g_g2[(size_t)u * HH2 + c];
    }
    acc += __shfl_xor_sync(0xffffffffu, acc, 16);
    if (half == 0) {
        float r = dv * acc + b2[c];
        g_h2[(size_t)v * HH2 + c] = fmaxf(r, 0.f);
    }
}

// ---------------- final: out = log_softmax(h2 @ Wl + bl), TF32 GEMM inputs ------
// v3: 4 nodes per pass (no register spills), no max-subtraction (logits O(1),
// exp cannot overflow), __expf/__logf, 3 syncs per batch.
#define WCOL 1536
#define FB2  64        // nodes per block (16 batches of 4)
#define FIN_SMEM ((16 * WCOL + WCOL + 64 + 48) * 4)
__global__ void __launch_bounds__(256, 2)
final_kernel(const float* __restrict__ Wl, const float* __restrict__ bl,
             float* __restrict__ out) {
    extern __shared__ float sm[];
    float* Wls = sm;                        // [16][1536]
    float* bls = Wls + 16 * WCOL;           // [1536]
    float* h2s = bls + WCOL;                // [16][4] k-major (8B-aligned)
    float* red = h2s + 64;                  // [48]: [0..31] partials, [32..35] lse
    const int tid = threadIdx.x, lane = tid & 31, wid = tid >> 5;

    for (int i = tid; i < 16 * WCOL; i += 256) {
        int k = i / WCOL, c = i - k * WCOL;
        Wls[i] = (c < FIN) ? tf32r(Wl[k * FIN + c]) : 0.f;
    }
    for (int c = tid; c < WCOL; c += 256) bls[c] = (c < FIN) ? bl[c] : -1e30f;

    for (int bt = 0; bt < 16; bt++) {
        const int v0 = blockIdx.x * FB2 + bt * 4;
        __syncthreads();                    // previous batch done with h2s/red
        if (tid < 64) {
            int k = tid >> 2, n = tid & 3;
            int v = v0 + n;
            h2s[k * 4 + n] = (v < NN) ? tf32r(g_h2[(size_t)v * HH2 + k]) : 0.f;
        }
        __syncthreads();

        unsigned long long acc[6][2];
        #pragma unroll
        for (int j = 0; j < 6; j++) { acc[j][0] = 0ull; acc[j][1] = 0ull; }

        #pragma unroll 4
        for (int k = 0; k < 16; k++) {
            unsigned long long hp0 = *(const unsigned long long*)(h2s + k * 4);
            unsigned long long hp1 = *(const unsigned long long*)(h2s + k * 4 + 2);
            #pragma unroll
            for (int j = 0; j < 6; j++) {
                unsigned long long wp = packf2(Wls[k * WCOL + j * 256 + tid]);
                ffma2(acc[j][0], hp0, wp);
                ffma2(acc[j][1], hp1, wp);
            }
        }

        float val[6][4];
        float ls[4] = {0.f, 0.f, 0.f, 0.f};
        #pragma unroll
        for (int j = 0; j < 6; j++) {
            float bb = bls[j * 256 + tid];
            float a0, a1, a2, a3;
            unpackf2(acc[j][0], a0, a1);
            unpackf2(acc[j][1], a2, a3);
            val[j][0] = a0 + bb; val[j][1] = a1 + bb;
            val[j][2] = a2 + bb; val[j][3] = a3 + bb;
            #pragma unroll
            for (int n = 0; n < 4; n++) ls[n] += __expf(val[j][n]);
        }
        #pragma unroll
        for (int n = 0; n < 4; n++)
            #pragma unroll
            for (int o = 16; o > 0; o >>= 1)
                ls[n] += __shfl_xor_sync(0xffffffffu, ls[n], o);
        if (lane == 0)
            #pragma unroll
            for (int n = 0; n < 4; n++) red[wid * 4 + n] = ls[n];
        __syncthreads();
        if (tid < 4) {
            float s = 0.f;
            #pragma unroll
            for (int w = 0; w < 8; w++) s += red[w * 4 + tid];
            red[32 + tid] = __logf(s);
        }
        __syncthreads();
        float lse[4];
        #pragma unroll
        for (int n = 0; n < 4; n++) lse[n] = red[32 + n];

        #pragma unroll
        for (int j = 0; j < 6; j++) {
            int col = j * 256 + tid;
            if (col < FIN) {
                #pragma unroll
                for (int n = 0; n < 4; n++) {
                    int v = v0 + n;
                    if (v < NN) out[(size_t)v * FIN + col] = val[j][n] - lse[n];
                }
            }
        }
    }
}

// ---------------- launch --------------------------------------------------------
static inline int cdiv(int a, int b) { return (a + b - 1) / b; }

extern "C" void kernel_launch(void* const* d_in, const int* in_sizes, int n_in,
                              void* d_out, int out_size) {
    const float* x  = (const float*)d_in[0];
    const float* W1 = (const float*)d_in[1];
    const float* b1 = (const float*)d_in[2];
    const float* W2 = (const float*)d_in[3];
    const float* b2 = (const float*)d_in[4];
    const float* Wl = (const float*)d_in[5];
    const float* bl = (const float*)d_in[6];
    const void*  ei = d_in[7];
    float* out = (float*)d_out;

    cudaFuncSetAttribute(final_kernel, cudaFuncAttributeMaxDynamicSharedMemorySize, FIN_SMEM);

    // gemm1 is my 4th launch: ncu (-s 5 -c 1 with ~2 harness launches ahead)
    // should capture it this round.
    detect_kernel<<<1, 1>>>((const unsigned int*)ei);
    convert_kernel<<<cdiv(2 * EE, 256), 256>>>(ei);
    init_kernel<<<cdiv(NN, 256), 256>>>();

    gemm1_kernel<<<cdiv(NN, 256), 256>>>(x, W1);

    degree_kernel<<<cdiv(EE, 256), 256>>>();
    int nblk = cdiv(NN, 1024);
    scan1_kernel<<<nblk, 1024>>>();          // also writes g_dis
    scan2_kernel<<<1, 32>>>(nblk);
    scan3_kernel<<<cdiv(NN + 1, 256), 256>>>();
    fill_kernel<<<cdiv(EE, 256), 256>>>();

    agg1_kernel<<<cdiv(NN * 32, 256), 256>>>(b1, W2);   // fused gemm2
    agg2_kernel<<<cdiv(NN * 32, 256), 256>>>(b2);
    final_kernel<<<cdiv(NN, FB2), 256, FIN_SMEM>>>(Wl, bl, out);
}

// round 8
// speedup vs baseline: 1.6964x; 1.5301x over previous
#include <cuda_runtime.h>
#include <cstdint>
#include <math.h>

#define NN   100000
#define FIN  1433
#define HH1  32
#define HH2  16
#define EE   3200000

// ---------------- scratch (__device__ globals; no allocations allowed) ----------
__device__ int   g_is64;
__device__ int   g_edges[2 * EE];
__device__ int   g_deg[NN];
__device__ float g_dis[NN];
__device__ int   g_rowptr[NN + 1];
__device__ int   g_fill[NN];
__device__ int   g_col[EE];
__device__ int   g_bsum[128];
__device__ float g_g1[NN * HH1];
__device__ float g_g2[NN * HH2];
__device__ float g_h2[NN * HH2];

// ---------------- f32x2 + tf32 helpers ------------------------------------------
__device__ __forceinline__ unsigned long long packf2(float x) {
    unsigned long long r;
    asm("mov.b64 %0, {%1, %1};" : "=l"(r) : "f"(x));
    return r;
}
__device__ __forceinline__ void ffma2(unsigned long long& d, unsigned long long a,
                                      unsigned long long b) {
    asm("fma.rn.f32x2 %0, %1, %2, %0;" : "+l"(d) : "l"(a), "l"(b));
}
__device__ __forceinline__ void unpackf2(unsigned long long p, float& lo, float& hi) {
    asm("mov.b64 {%0, %1}, %2;" : "=f"(lo), "=f"(hi) : "l"(p));
}
__device__ __forceinline__ float tf32r(float x) {
    float r;
    asm("cvt.rna.tf32.f32 %0, %1;" : "=f"(r) : "f"(x));
    return r;
}

// ---------------- edge dtype detect + convert -----------------------------------
__global__ void detect_kernel(const unsigned int* __restrict__ p) {
    int is64 = 1;
    for (int i = 0; i < 64; i++)
        if (p[2 * i + 1] != 0u) { is64 = 0; break; }
    g_is64 = is64;
}

__global__ void convert_kernel(const void* __restrict__ p) {
    int i = blockIdx.x * blockDim.x + threadIdx.x;
    if (i >= 2 * EE) return;
    int v;
    if (g_is64) v = (int)((const long long*)p)[i];
    else        v = ((const int*)p)[i];
    g_edges[i] = v;
}

// ---------------- degree / normalization / CSR ----------------------------------
__global__ void init_kernel() {
    int v = blockIdx.x * blockDim.x + threadIdx.x;
    if (v < NN) { g_deg[v] = 1; g_fill[v] = 0; }
}

__global__ void degree_kernel() {
    int e = blockIdx.x * blockDim.x + threadIdx.x;
    if (e < EE) atomicAdd(&g_deg[g_edges[EE + e]], 1);
}

__global__ void scan1_kernel() {
    __shared__ int s[1024];
    int tid = threadIdx.x;
    int v = blockIdx.x * 1024 + tid;
    int d = (v < NN) ? g_deg[v] : 1;
    int val = (v < NN) ? (d - 1) : 0;
    s[tid] = val;
    __syncthreads();
    for (int off = 1; off < 1024; off <<= 1) {
        int t = (tid >= off) ? s[tid - off] : 0;
        __syncthreads();
        s[tid] += t;
        __syncthreads();
    }
    if (v < NN) {
        g_rowptr[v] = s[tid] - val;
        g_dis[v] = rsqrtf((float)d);
    }
    if (tid == 1023) g_bsum[blockIdx.x] = s[1023];
}

__global__ void scan2_kernel(int nblk) {
    if (threadIdx.x == 0 && blockIdx.x == 0) {
        int run = 0;
        for (int i = 0; i < nblk; i++) { int t = g_bsum[i]; g_bsum[i] = run; run += t; }
    }
}

__global__ void scan3_kernel() {
    int v = blockIdx.x * blockDim.x + threadIdx.x;
    if (v < NN)       g_rowptr[v] += g_bsum[v >> 10];
    else if (v == NN) g_rowptr[NN] = EE;
}

__global__ void fill_kernel() {
    int e = blockIdx.x * blockDim.x + threadIdx.x;
    if (e >= EE) return;
    int v   = g_edges[EE + e];
    int pos = atomicAdd(&g_fill[v], 1);
    g_col[g_rowptr[v] + pos] = g_edges[e];
}

// ---------------- GEMM1 v3: g1 = x @ W1  [100000,1433]x[1433,32] ----------------
// No reg cap (compiler ~100 regs) -> deep software pipelining. Next x-tile and
// next W-tile prefetched into registers DURING compute; STS folded into the
// sync window. FFMA2 floor ~134us chip-wide; target fma-pipe >40%.
__global__ void __launch_bounds__(256)
gemm1_kernel(const float* __restrict__ x, const float* __restrict__ W1) {
    __shared__ float xs[256 * 33];
    __shared__ __align__(16) float Ws[32 * 32];
    const int tid = threadIdx.x;
    const int row0 = blockIdx.x * 256;

    // prefetch tile 0 (k0 = 0; cols 0..31 < FIN always)
    float xr[32];
    #pragma unroll
    for (int i = 0; i < 32; i++) {
        int idx = i * 256 + tid;
        int r = idx >> 5, c = idx & 31;
        int gr = row0 + r;
        xr[i] = (gr < NN) ? x[(size_t)gr * FIN + c] : 0.f;
    }
    float4 wreg = *(const float4*)(W1 + tid * 4);   // rows 0..31 all < FIN

    unsigned long long acc[16];
    #pragma unroll
    for (int i = 0; i < 16; i++) acc[i] = 0ull;

    const int NT = (FIN + 31) / 32;   // 45
    for (int t = 0; t < NT; t++) {
        __syncthreads();               // previous compute done reading xs/Ws
        #pragma unroll
        for (int i = 0; i < 32; i++) {
            int idx = i * 256 + tid;
            int r = idx >> 5, c = idx & 31;
            xs[r * 33 + c] = tf32r(xr[i]);
        }
        {
            float4 w;
            w.x = tf32r(wreg.x); w.y = tf32r(wreg.y);
            w.z = tf32r(wreg.z); w.w = tf32r(wreg.w);
            *(float4*)&Ws[tid * 4] = w;
        }
        __syncthreads();

        if (t + 1 < NT) {              // prefetch next tiles during compute
            const int k0n = (t + 1) * 32;
            #pragma unroll
            for (int i = 0; i < 32; i++) {
                int idx = i * 256 + tid;
                int r = idx >> 5, c = idx & 31;
                int gr = row0 + r, k = k0n + c;
                xr[i] = (gr < NN && k < FIN) ? x[(size_t)gr * FIN + k] : 0.f;
            }
            int i = tid * 4;
            int krow = k0n + (i >> 5);
            wreg = make_float4(0.f, 0.f, 0.f, 0.f);
            if (krow < FIN) wreg = *(const float4*)(W1 + (size_t)k0n * 32 + i);
        }

        #pragma unroll 8
        for (int j = 0; j < 32; j++) {
            unsigned long long x2 = packf2(xs[tid * 33 + j]);
            const ulonglong2* wr = (const ulonglong2*)(Ws + j * 32);
            #pragma unroll
            for (int q = 0; q < 8; q++) {
                ulonglong2 w = wr[q];
                ffma2(acc[2 * q],     x2, w.x);
                ffma2(acc[2 * q + 1], x2, w.y);
            }
        }
    }
    int row = row0 + tid;
    if (row < NN) {
        ulonglong2* o = (ulonglong2*)(g_g1 + (size_t)row * HH1);
        #pragma unroll
        for (int q = 0; q < 8; q++) o[q] = make_ulonglong2(acc[2 * q], acc[2 * q + 1]);
    }
}

// ------- aggregation layer 1 + fused GEMM2 (warp per node) ----------------------
__global__ void agg1_kernel(const float* __restrict__ b1, const float* __restrict__ W2) {
    __shared__ float W2s[32 * 16];
    __shared__ float b1s[32];
    {
        int tid = threadIdx.x;
        for (int i = tid; i < 32 * 16; i += 256) W2s[i] = tf32r(W2[i]);
        if (tid < 32) b1s[tid] = b1[tid];
    }
    __syncthreads();

    int t = blockIdx.x * blockDim.x + threadIdx.x;
    int v = t >> 5, lane = t & 31;
    if (v >= NN) return;
    float dv  = g_dis[v];
    float acc = dv * g_g1[(size_t)v * HH1 + lane];
    int b = g_rowptr[v], e = g_rowptr[v + 1];
    int i = b;
    for (; i + 4 <= e; i += 4) {
        int u0 = g_col[i], u1 = g_col[i + 1], u2 = g_col[i + 2], u3 = g_col[i + 3];
        float d0 = g_dis[u0], d1 = g_dis[u1], d2 = g_dis[u2], d3 = g_dis[u3];
        acc += d0 * g_g1[(size_t)u0 * HH1 + lane];
        acc += d1 * g_g1[(size_t)u1 * HH1 + lane];
        acc += d2 * g_g1[(size_t)u2 * HH1 + lane];
        acc += d3 * g_g1[(size_t)u3 * HH1 + lane];
    }
    for (; i < e; i++) {
        int u = g_col[i];
        acc += g_dis[u] * g_g1[(size_t)u * HH1 + lane];
    }
    float h = tf32r(fmaxf(dv * acc + b1s[lane], 0.f));

    int c = lane & 15, half = lane >> 4;
    float o = 0.f;
    #pragma unroll
    for (int k = 0; k < 16; k++) {
        int kk = half * 16 + k;
        float hv = __shfl_sync(0xffffffffu, h, kk);
        o += hv * W2s[kk * 16 + c];
    }
    o += __shfl_xor_sync(0xffffffffu, o, 16);
    if (half == 0) g_g2[(size_t)v * HH2 + c] = o;
}

// ---------------- aggregation layer 2 -------------------------------------------
__global__ void agg2_kernel(const float* __restrict__ b2) {
    int t = blockIdx.x * blockDim.x + threadIdx.x;
    int v = t >> 5, lane = t & 31;
    if (v >= NN) return;
    int c = lane & 15, half = lane >> 4;
    float dv  = g_dis[v];
    float acc = (half == 0) ? dv * g_g2[(size_t)v * HH2 + c] : 0.f;
    int b = g_rowptr[v], e = g_rowptr[v + 1];
    for (int i = b + half; i < e; i += 2) {
        int u = g_col[i];
        acc += g_dis[u] * g_g2[(size_t)u * HH2 + c];
    }
    acc += __shfl_xor_sync(0xffffffffu, acc, 16);
    if (half == 0) {
        float r = dv * acc + b2[c];
        g_h2[(size_t)v * HH2 + c] = fmaxf(r, 0.f);
    }
}

// ---------------- final: out = log_softmax(h2 @ Wl + bl) ------------------------
#define WCOL 1536
#define FB2  64
#define FIN_SMEM ((16 * WCOL + WCOL + 64 + 48) * 4)
__global__ void __launch_bounds__(256, 2)
final_kernel(const float* __restrict__ Wl, const float* __restrict__ bl,
             float* __restrict__ out) {
    extern __shared__ float sm[];
    float* Wls = sm;
    float* bls = Wls + 16 * WCOL;
    float* h2s = bls + WCOL;
    float* red = h2s + 64;
    const int tid = threadIdx.x, lane = tid & 31, wid = tid >> 5;

    for (int i = tid; i < 16 * WCOL; i += 256) {
        int k = i / WCOL, c = i - k * WCOL;
        Wls[i] = (c < FIN) ? tf32r(Wl[k * FIN + c]) : 0.f;
    }
    for (int c = tid; c < WCOL; c += 256) bls[c] = (c < FIN) ? bl[c] : -1e30f;

    for (int bt = 0; bt < 16; bt++) {
        const int v0 = blockIdx.x * FB2 + bt * 4;
        __syncthreads();
        if (tid < 64) {
            int k = tid >> 2, n = tid & 3;
            int v = v0 + n;
            h2s[k * 4 + n] = (v < NN) ? tf32r(g_h2[(size_t)v * HH2 + k]) : 0.f;
        }
        __syncthreads();

        unsigned long long acc[6][2];
        #pragma unroll
        for (int j = 0; j < 6; j++) { acc[j][0] = 0ull; acc[j][1] = 0ull; }

        #pragma unroll 4
        for (int k = 0; k < 16; k++) {
            unsigned long long hp0 = *(const unsigned long long*)(h2s + k * 4);
            unsigned long long hp1 = *(const unsigned long long*)(h2s + k * 4 + 2);
            #pragma unroll
            for (int j = 0; j < 6; j++) {
                unsigned long long wp = packf2(Wls[k * WCOL + j * 256 + tid]);
                ffma2(acc[j][0], hp0, wp);
                ffma2(acc[j][1], hp1, wp);
            }
        }

        float val[6][4];
        float ls[4] = {0.f, 0.f, 0.f, 0.f};
        #pragma unroll
        for (int j = 0; j < 6; j++) {
            float bb = bls[j * 256 + tid];
            float a0, a1, a2, a3;
            unpackf2(acc[j][0], a0, a1);
            unpackf2(acc[j][1], a2, a3);
            val[j][0] = a0 + bb; val[j][1] = a1 + bb;
            val[j][2] = a2 + bb; val[j][3] = a3 + bb;
            #pragma unroll
            for (int n = 0; n < 4; n++) ls[n] += __expf(val[j][n]);
        }
        #pragma unroll
        for (int n = 0; n < 4; n++)
            #pragma unroll
            for (int o = 16; o > 0; o >>= 1)
                ls[n] += __shfl_xor_sync(0xffffffffu, ls[n], o);
        if (lane == 0)
            #pragma unroll
            for (int n = 0; n < 4; n++) red[wid * 4 + n] = ls[n];
        __syncthreads();
        if (tid < 4) {
            float s = 0.f;
            #pragma unroll
            for (int w = 0; w < 8; w++) s += red[w * 4 + tid];
            red[32 + tid] = __logf(s);
        }
        __syncthreads();
        float lse[4];
        #pragma unroll
        for (int n = 0; n < 4; n++) lse[n] = red[32 + n];

        #pragma unroll
        for (int j = 0; j < 6; j++) {
            int col = j * 256 + tid;
            if (col < FIN) {
                #pragma unroll
                for (int n = 0; n < 4; n++) {
                    int v = v0 + n;
                    if (v < NN) out[(size_t)v * FIN + col] = val[j][n] - lse[n];
                }
            }
        }
    }
}

// ---------------- launch --------------------------------------------------------
static inline int cdiv(int a, int b) { return (a + b - 1) / b; }

extern "C" void kernel_launch(void* const* d_in, const int* in_sizes, int n_in,
                              void* d_out, int out_size) {
    const float* x  = (const float*)d_in[0];
    const float* W1 = (const float*)d_in[1];
    const float* b1 = (const float*)d_in[2];
    const float* W2 = (const float*)d_in[3];
    const float* b2 = (const float*)d_in[4];
    const float* Wl = (const float*)d_in[5];
    const float* bl = (const float*)d_in[6];
    const void*  ei = d_in[7];
    float* out = (float*)d_out;

    cudaFuncSetAttribute(final_kernel, cudaFuncAttributeMaxDynamicSharedMemorySize, FIN_SMEM);

    // gemm1 is my 4th launch -> profiled by ncu (-s 5 -c 1) next round
    detect_kernel<<<1, 1>>>((const unsigned int*)ei);
    convert_kernel<<<cdiv(2 * EE, 256), 256>>>(ei);
    init_kernel<<<cdiv(NN, 256), 256>>>();

    gemm1_kernel<<<cdiv(NN, 256), 256>>>(x, W1);

    degree_kernel<<<cdiv(EE, 256), 256>>>();
    int nblk = cdiv(NN, 1024);
    scan1_kernel<<<nblk, 1024>>>();
    scan2_kernel<<<1, 32>>>(nblk);
    scan3_kernel<<<cdiv(NN + 1, 256), 256>>>();
    fill_kernel<<<cdiv(EE, 256), 256>>>();

    agg1_kernel<<<cdiv(NN * 32, 256), 256>>>(b1, W2);
    agg2_kernel<<<cdiv(NN * 32, 256), 256>>>(b2);
    final_kernel<<<cdiv(NN, FB2), 256, FIN_SMEM>>>(Wl, bl, out);
}

// round 9
// speedup vs baseline: 2.0610x; 1.2149x over previous
#include <cuda_runtime.h>
#include <cstdint>
#include <math.h>

#define NN   100000
#define FIN  1433
#define HH1  32
#define HH2  16
#define EE   3200000

// ---------------- scratch (__device__ globals; no allocations allowed) ----------
__device__ int   g_is64;
__device__ int   g_edges[2 * EE];
__device__ int   g_deg[NN];
__device__ float g_dis[NN];
__device__ int   g_rowptr[NN + 1];
__device__ int   g_fill[NN];
__device__ int   g_col[EE];
__device__ int   g_bsum[128];
__device__ float g_g1[NN * HH1];
__device__ float g_g2[NN * HH2];
__device__ float g_h2[NN * HH2];

// ---------------- f32x2 + tf32 helpers ------------------------------------------
__device__ __forceinline__ unsigned long long packf2(float x) {
    unsigned long long r;
    asm("mov.b64 %0, {%1, %1};" : "=l"(r) : "f"(x));
    return r;
}
__device__ __forceinline__ void ffma2(unsigned long long& d, unsigned long long a,
                                      unsigned long long b) {
    asm("fma.rn.f32x2 %0, %1, %2, %0;" : "+l"(d) : "l"(a), "l"(b));
}
__device__ __forceinline__ void unpackf2(unsigned long long p, float& lo, float& hi) {
    asm("mov.b64 {%0, %1}, %2;" : "=f"(lo), "=f"(hi) : "l"(p));
}
__device__ __forceinline__ float tf32r(float x) {
    float r;
    asm("cvt.rna.tf32.f32 %0, %1;" : "=f"(r) : "f"(x));
    return r;
}
// Legacy tensor-core MMA: m16n8k8 tf32 (sm_80+, valid on plain sm_103 target).
__device__ __forceinline__ void mma_tf32(float* d, const uint32_t* a, const uint32_t* b) {
    asm volatile(
        "mma.sync.aligned.m16n8k8.row.col.f32.tf32.tf32.f32 "
        "{%0,%1,%2,%3}, {%4,%5,%6,%7}, {%8,%9}, {%0,%1,%2,%3};"
        : "+f"(d[0]), "+f"(d[1]), "+f"(d[2]), "+f"(d[3])
        : "r"(a[0]), "r"(a[1]), "r"(a[2]), "r"(a[3]), "r"(b[0]), "r"(b[1]));
}

// ---------------- edge dtype detect + convert -----------------------------------
__global__ void detect_kernel(const unsigned int* __restrict__ p) {
    int is64 = 1;
    for (int i = 0; i < 64; i++)
        if (p[2 * i + 1] != 0u) { is64 = 0; break; }
    g_is64 = is64;
}

__global__ void convert_kernel(const void* __restrict__ p) {
    int i = blockIdx.x * blockDim.x + threadIdx.x;
    if (i >= 2 * EE) return;
    int v;
    if (g_is64) v = (int)((const long long*)p)[i];
    else        v = ((const int*)p)[i];
    g_edges[i] = v;
}

// ---------------- degree / normalization / CSR ----------------------------------
__global__ void init_kernel() {
    int v = blockIdx.x * blockDim.x + threadIdx.x;
    if (v < NN) { g_deg[v] = 1; g_fill[v] = 0; }
}

__global__ void degree_kernel() {
    int e = blockIdx.x * blockDim.x + threadIdx.x;
    if (e < EE) atomicAdd(&g_deg[g_edges[EE + e]], 1);
}

__global__ void scan1_kernel() {
    __shared__ int s[1024];
    int tid = threadIdx.x;
    int v = blockIdx.x * 1024 + tid;
    int d = (v < NN) ? g_deg[v] : 1;
    int val = (v < NN) ? (d - 1) : 0;
    s[tid] = val;
    __syncthreads();
    for (int off = 1; off < 1024; off <<= 1) {
        int t = (tid >= off) ? s[tid - off] : 0;
        __syncthreads();
        s[tid] += t;
        __syncthreads();
    }
    if (v < NN) {
        g_rowptr[v] = s[tid] - val;
        g_dis[v] = rsqrtf((float)d);
    }
    if (tid == 1023) g_bsum[blockIdx.x] = s[1023];
}

__global__ void scan2_kernel(int nblk) {
    if (threadIdx.x == 0 && blockIdx.x == 0) {
        int run = 0;
        for (int i = 0; i < nblk; i++) { int t = g_bsum[i]; g_bsum[i] = run; run += t; }
    }
}

__global__ void scan3_kernel() {
    int v = blockIdx.x * blockDim.x + threadIdx.x;
    if (v < NN)       g_rowptr[v] += g_bsum[v >> 10];
    else if (v == NN) g_rowptr[NN] = EE;
}

__global__ void fill_kernel() {
    int e = blockIdx.x * blockDim.x + threadIdx.x;
    if (e >= EE) return;
    int v   = g_edges[EE + e];
    int pos = atomicAdd(&g_fill[v], 1);
    g_col[g_rowptr[v] + pos] = g_edges[e];
}

// ---------------- GEMM1 v4 (mma.sync tf32): g1 = x @ W1 -------------------------
// Block: 256 thr (8 warps), tile 256 rows x 32 cols. Warp: 32 rows (2 m16 x 4 n8).
// xs [256][36] (stride-36 -> conflict-free coalesced store AND frag reads),
// Ws transposed [n=32][36] (B-frag bank = lane). tf32 rounding on STS side.
// Prefetch next x/W tiles in registers during compute (R8 skeleton).
#define XS_STRIDE 36
__global__ void __launch_bounds__(256)
gemm1_kernel(const float* __restrict__ x, const float* __restrict__ W1) {
    __shared__ float xs[256 * XS_STRIDE];
    __shared__ float Ws[32 * XS_STRIDE];
    const int tid = threadIdx.x;
    const int wid = tid >> 5;
    const int lane = tid & 31;
    const int grp = lane >> 2, tig = lane & 3;
    const int woff = wid * 32;                 // warp's row offset within block
    const int row0 = blockIdx.x * 256;

    // prefetch tile 0 (k0 = 0; cols 0..31 < FIN always)
    float xr[32];
    #pragma unroll
    for (int i = 0; i < 32; i++) {
        int idx = i * 256 + tid;
        int r = idx >> 5, c = idx & 31;
        int gr = row0 + r;
        xr[i] = (gr < NN) ? x[(size_t)gr * FIN + c] : 0.f;
    }
    float4 wreg = *(const float4*)(W1 + tid * 4);   // k rows 0..31 < FIN

    float acc[2][4][4];
    #pragma unroll
    for (int m = 0; m < 2; m++)
        #pragma unroll
        for (int n = 0; n < 4; n++)
            #pragma unroll
            for (int q = 0; q < 4; q++) acc[m][n][q] = 0.f;

    const int NT = (FIN + 31) / 32;   // 45
    for (int t = 0; t < NT; t++) {
        __syncthreads();               // previous compute done reading xs/Ws
        #pragma unroll
        for (int i = 0; i < 32; i++) {
            int idx = i * 256 + tid;
            int r = idx >> 5, c = idx & 31;
            xs[r * XS_STRIDE + c] = tf32r(xr[i]);
        }
        {   // W tile transposed: Ws[n][k]
            int i = tid * 4;
            int k = i >> 5, n0 = i & 31;
            Ws[(n0 + 0) * XS_STRIDE + k] = tf32r(wreg.x);
            Ws[(n0 + 1) * XS_STRIDE + k] = tf32r(wreg.y);
            Ws[(n0 + 2) * XS_STRIDE + k] = tf32r(wreg.z);
            Ws[(n0 + 3) * XS_STRIDE + k] = tf32r(wreg.w);
        }
        __syncthreads();

        if (t + 1 < NT) {              // prefetch next tiles during compute
            const int k0n = (t + 1) * 32;
            #pragma unroll
            for (int i = 0; i < 32; i++) {
                int idx = i * 256 + tid;
                int r = idx >> 5, c = idx & 31;
                int gr = row0 + r, k = k0n + c;
                xr[i] = (gr < NN && k < FIN) ? x[(size_t)gr * FIN + k] : 0.f;
            }
            int i = tid * 4;
            int krow = k0n + (i >> 5);
            wreg = make_float4(0.f, 0.f, 0.f, 0.f);
            if (krow < FIN) wreg = *(const float4*)(W1 + (size_t)k0n * 32 + i);
        }

        #pragma unroll
        for (int s = 0; s < 4; s++) {  // four k8 steps
            const int k8 = s * 8;
            uint32_t afr[2][4], bfr[4][2];
            #pragma unroll
            for (int m = 0; m < 2; m++) {
                int r = woff + m * 16 + grp;
                afr[m][0] = __float_as_uint(xs[(r)     * XS_STRIDE + k8 + tig]);
                afr[m][1] = __float_as_uint(xs[(r + 8) * XS_STRIDE + k8 + tig]);
                afr[m][2] = __float_as_uint(xs[(r)     * XS_STRIDE + k8 + tig + 4]);
                afr[m][3] = __float_as_uint(xs[(r + 8) * XS_STRIDE + k8 + tig + 4]);
            }
            #pragma unroll
            for (int n = 0; n < 4; n++) {
                int nn = n * 8 + grp;
                bfr[n][0] = __float_as_uint(Ws[nn * XS_STRIDE + k8 + tig]);
                bfr[n][1] = __float_as_uint(Ws[nn * XS_STRIDE + k8 + tig + 4]);
            }
            #pragma unroll
            for (int m = 0; m < 2; m++)
                #pragma unroll
                for (int n = 0; n < 4; n++)
                    mma_tf32(acc[m][n], afr[m], bfr[n]);
        }
    }

    // store D: thread holds rows grp, grp+8 per m16-tile; cols 2*tig, 2*tig+1 per n8
    #pragma unroll
    for (int m = 0; m < 2; m++) {
        int r0 = row0 + woff + m * 16 + grp;
        #pragma unroll
        for (int h = 0; h < 2; h++) {
            int r = r0 + h * 8;
            if (r < NN) {
                float* o = g_g1 + (size_t)r * HH1 + 2 * tig;
                #pragma unroll
                for (int n = 0; n < 4; n++)
                    *(float2*)(o + n * 8) =
                        make_float2(acc[m][n][2 * h], acc[m][n][2 * h + 1]);
            }
        }
    }
}

// ------- aggregation layer 1 + fused GEMM2 (warp per node) ----------------------
__global__ void agg1_kernel(const float* __restrict__ b1, const float* __restrict__ W2) {
    __shared__ float W2s[32 * 16];
    __shared__ float b1s[32];
    {
        int tid = threadIdx.x;
        for (int i = tid; i < 32 * 16; i += 256) W2s[i] = tf32r(W2[i]);
        if (tid < 32) b1s[tid] = b1[tid];
    }
    __syncthreads();

    int t = blockIdx.x * blockDim.x + threadIdx.x;
    int v = t >> 5, lane = t & 31;
    if (v >= NN) return;
    float dv  = g_dis[v];
    float acc = dv * g_g1[(size_t)v * HH1 + lane];
    int b = g_rowptr[v], e = g_rowptr[v + 1];
    int i = b;
    for (; i + 4 <= e; i += 4) {
        int u0 = g_col[i], u1 = g_col[i + 1], u2 = g_col[i + 2], u3 = g_col[i + 3];
        float d0 = g_dis[u0], d1 = g_dis[u1], d2 = g_dis[u2], d3 = g_dis[u3];
        acc += d0 * g_g1[(size_t)u0 * HH1 + lane];
        acc += d1 * g_g1[(size_t)u1 * HH1 + lane];
        acc += d2 * g_g1[(size_t)u2 * HH1 + lane];
        acc += d3 * g_g1[(size_t)u3 * HH1 + lane];
    }
    for (; i < e; i++) {
        int u = g_col[i];
        acc += g_dis[u] * g_g1[(size_t)u * HH1 + lane];
    }
    float h = tf32r(fmaxf(dv * acc + b1s[lane], 0.f));

    int c = lane & 15, half = lane >> 4;
    float o = 0.f;
    #pragma unroll
    for (int k = 0; k < 16; k++) {
        int kk = half * 16 + k;
        float hv = __shfl_sync(0xffffffffu, h, kk);
        o += hv * W2s[kk * 16 + c];
    }
    o += __shfl_xor_sync(0xffffffffu, o, 16);
    if (half == 0) g_g2[(size_t)v * HH2 + c] = o;
}

// ---------------- aggregation layer 2 -------------------------------------------
__global__ void agg2_kernel(const float* __restrict__ b2) {
    int t = blockIdx.x * blockDim.x + threadIdx.x;
    int v = t >> 5, lane = t & 31;
    if (v >= NN) return;
    int c = lane & 15, half = lane >> 4;
    float dv  = g_dis[v];
    float acc = (half == 0) ? dv * g_g2[(size_t)v * HH2 + c] : 0.f;
    int b = g_rowptr[v], e = g_rowptr[v + 1];
    for (int i = b + half; i < e; i += 2) {
        int u = g_col[i];
        acc += g_dis[u] * g_g2[(size_t)u * HH2 + c];
    }
    acc += __shfl_xor_sync(0xffffffffu, acc, 16);
    if (half == 0) {
        float r = dv * acc + b2[c];
        g_h2[(size_t)v * HH2 + c] = fmaxf(r, 0.f);
    }
}

// ---------------- final: out = log_softmax(h2 @ Wl + bl) ------------------------
#define WCOL 1536
#define FB2  64
#define FIN_SMEM ((16 * WCOL + WCOL + 64 + 48) * 4)
__global__ void __launch_bounds__(256, 2)
final_kernel(const float* __restrict__ Wl, const float* __restrict__ bl,
             float* __restrict__ out) {
    extern __shared__ float sm[];
    float* Wls = sm;
    float* bls = Wls + 16 * WCOL;
    float* h2s = bls + WCOL;
    float* red = h2s + 64;
    const int tid = threadIdx.x, lane = tid & 31, wid = tid >> 5;

    for (int i = tid; i < 16 * WCOL; i += 256) {
        int k = i / WCOL, c = i - k * WCOL;
        Wls[i] = (c < FIN) ? tf32r(Wl[k * FIN + c]) : 0.f;
    }
    for (int c = tid; c < WCOL; c += 256) bls[c] = (c < FIN) ? bl[c] : -1e30f;

    for (int bt = 0; bt < 16; bt++) {
        const int v0 = blockIdx.x * FB2 + bt * 4;
        __syncthreads();
        if (tid < 64) {
            int k = tid >> 2, n = tid & 3;
            int v = v0 + n;
            h2s[k * 4 + n] = (v < NN) ? tf32r(g_h2[(size_t)v * HH2 + k]) : 0.f;
        }
        __syncthreads();

        unsigned long long acc[6][2];
        #pragma unroll
        for (int j = 0; j < 6; j++) { acc[j][0] = 0ull; acc[j][1] = 0ull; }

        #pragma unroll 4
        for (int k = 0; k < 16; k++) {
            unsigned long long hp0 = *(const unsigned long long*)(h2s + k * 4);
            unsigned long long hp1 = *(const unsigned long long*)(h2s + k * 4 + 2);
            #pragma unroll
            for (int j = 0; j < 6; j++) {
                unsigned long long wp = packf2(Wls[k * WCOL + j * 256 + tid]);
                ffma2(acc[j][0], hp0, wp);
                ffma2(acc[j][1], hp1, wp);
            }
        }

        float val[6][4];
        float ls[4] = {0.f, 0.f, 0.f, 0.f};
        #pragma unroll
        for (int j = 0; j < 6; j++) {
            float bb = bls[j * 256 + tid];
            float a0, a1, a2, a3;
            unpackf2(acc[j][0], a0, a1);
            unpackf2(acc[j][1], a2, a3);
            val[j][0] = a0 + bb; val[j][1] = a1 + bb;
            val[j][2] = a2 + bb; val[j][3] = a3 + bb;
            #pragma unroll
            for (int n = 0; n < 4; n++) ls[n] += __expf(val[j][n]);
        }
        #pragma unroll
        for (int n = 0; n < 4; n++)
            #pragma unroll
            for (int o = 16; o > 0; o >>= 1)
                ls[n] += __shfl_xor_sync(0xffffffffu, ls[n], o);
        if (lane == 0)
            #pragma unroll
            for (int n = 0; n < 4; n++) red[wid * 4 + n] = ls[n];
        __syncthreads();
        if (tid < 4) {
            float s = 0.f;
            #pragma unroll
            for (int w = 0; w < 8; w++) s += red[w * 4 + tid];
            red[32 + tid] = __logf(s);
        }
        __syncthreads();
        float lse[4];
        #pragma unroll
        for (int n = 0; n < 4; n++) lse[n] = red[32 + n];

        #pragma unroll
        for (int j = 0; j < 6; j++) {
            int col = j * 256 + tid;
            if (col < FIN) {
                #pragma unroll
                for (int n = 0; n < 4; n++) {
                    int v = v0 + n;
                    if (v < NN) out[(size_t)v * FIN + col] = val[j][n] - lse[n];
                }
            }
        }
    }
}

// ---------------- launch --------------------------------------------------------
static inline int cdiv(int a, int b) { return (a + b - 1) / b; }

extern "C" void kernel_launch(void* const* d_in, const int* in_sizes, int n_in,
                              void* d_out, int out_size) {
    const float* x  = (const float*)d_in[0];
    const float* W1 = (const float*)d_in[1];
    const float* b1 = (const float*)d_in[2];
    const float* W2 = (const float*)d_in[3];
    const float* b2 = (const float*)d_in[4];
    const float* Wl = (const float*)d_in[5];
    const float* bl = (const float*)d_in[6];
    const void*  ei = d_in[7];
    float* out = (float*)d_out;

    cudaFuncSetAttribute(final_kernel, cudaFuncAttributeMaxDynamicSharedMemorySize, FIN_SMEM);

    // gemm1 is my 4th launch -> profiled by ncu next round
    detect_kernel<<<1, 1>>>((const unsigned int*)ei);
    convert_kernel<<<cdiv(2 * EE, 256), 256>>>(ei);
    init_kernel<<<cdiv(NN, 256), 256>>>();

    gemm1_kernel<<<cdiv(NN, 256), 256>>>(x, W1);

    degree_kernel<<<cdiv(EE, 256), 256>>>();
    int nblk = cdiv(NN, 1024);
    scan1_kernel<<<nblk, 1024>>>();
    scan2_kernel<<<1, 32>>>(nblk);
    scan3_kernel<<<cdiv(NN + 1, 256), 256>>>();
    fill_kernel<<<cdiv(EE, 256), 256>>>();

    agg1_kernel<<<cdiv(NN * 32, 256), 256>>>(b1, W2);
    agg2_kernel<<<cdiv(NN * 32, 256), 256>>>(b2);
    final_kernel<<<cdiv(NN, FB2), 256, FIN_SMEM>>>(Wl, bl, out);
}